// round 11
// baseline (speedup 1.0000x reference)
#include <cuda_runtime.h>
#include <cuda_fp16.h>

#define NV   8
#define C_CH 32
#define H_F  128
#define W_F  128
#define HW_F (H_F * W_F)
#define RESO 64

#define VOXEL_F ((float)(0.3/64.0))
#define HALF_F  ((float)(0.3/128.0))

typedef unsigned long long u64;
typedef unsigned u32;

// ---- helpers ----
__device__ __forceinline__ u32 pack_h2(float lo, float hi) {
    u32 r; asm("cvt.rn.f16x2.f32 %0, %1, %2;" : "=r"(r) : "f"(hi), "f"(lo)); return r;
}
__device__ __forceinline__ float rhalf(float x) {
    return __half2float(__float2half_rn(x));
}
__device__ __forceinline__ void ldsm_x4(u32& r0, u32& r1, u32& r2, u32& r3, u32 addr) {
    asm volatile("ldmatrix.sync.aligned.m8n8.x4.shared.b16 {%0,%1,%2,%3}, [%4];"
                 : "=r"(r0), "=r"(r1), "=r"(r2), "=r"(r3) : "r"(addr));
}
__device__ __forceinline__ void mma16816(float* c, const u32* a, u32 b0, u32 b1) {
    asm volatile("mma.sync.aligned.m16n8k16.row.col.f32.f16.f16.f32 "
                 "{%0,%1,%2,%3}, {%4,%5,%6,%7}, {%8,%9}, {%0,%1,%2,%3};"
                 : "+f"(c[0]), "+f"(c[1]), "+f"(c[2]), "+f"(c[3])
                 : "r"(a[0]), "r"(a[1]), "r"(a[2]), "r"(a[3]), "r"(b0), "r"(b1));
}

// Scratch
__device__ __align__(16) u32 g_Gh[4 * NV * HW_F * 4];   // fp16 plane-split G
__device__ float g_msum[NV * RESO * RESO];
__device__ __align__(16) u32 g_frag[4 * 32 * 4];        // fv_main per-lane frags (4 uint4/lane)
__device__ float g_M[NV * 12];

#define GEMM_BLOCKS 512
#define MSUM_BLOCKS 128
#define ROWB 80

// ---------------------------------------------------------------------------
// Prep kernel: [0,512) HMMA per-pixel GEMM G = feats@W1+b1 (fp16 store,
// W1 hi+lo exact); [512,640) msum; block 640 = fv_main fragment/M precompute.
// ---------------------------------------------------------------------------
__global__ __launch_bounds__(256, 3)
void prep_kernel(const float* __restrict__ feats,
                 const float* __restrict__ W1,
                 const float* __restrict__ b1,
                 const float* __restrict__ Ks,
                 const float* __restrict__ poses,
                 const float* __restrict__ bbox,
                 const int* __restrict__ ph,
                 const int* __restrict__ pw,
                 const float* __restrict__ W2, const float* __restrict__ b2,
                 const float* __restrict__ W3, const float* __restrict__ b3) {
    int tid = threadIdx.x;
    if (blockIdx.x < GEMM_BLOCKS) {
        __shared__ __align__(16) uint4 sFragW[8][32];   // [hl*4+kt*2+ntp][lane]
        __shared__ __align__(16) uint4 sFragB[2][32];
        __shared__ __align__(16) unsigned char sStage[8][32 * ROWB];

        int wid  = tid >> 5;
        int lane = tid & 31;
        int p0 = blockIdx.x * 256 + wid * 32;
        int v  = p0 >> 14;
        int pl = p0 & (HW_F - 1);
        const float* fp = feats + (size_t)v * C_CH * HW_F + pl + lane;

        // coalesced channel loads -> fp16 -> staging row
        u32 hq[16];
#pragma unroll
        for (int c2 = 0; c2 < 16; c2++) {
            float f0 = fp[(2 * c2    ) * HW_F];
            float f1 = fp[(2 * c2 + 1) * HW_F];
            hq[c2] = pack_h2(f0, f1);
        }
        {
            uint4* myrow = (uint4*)(sStage[wid] + lane * ROWB);
#pragma unroll
            for (int q = 0; q < 4; q++)
                myrow[q] = make_uint4(hq[q*4+0], hq[q*4+1], hq[q*4+2], hq[q*4+3]);
        }

        // W1/b1 fragments: each warp builds its own combo (parallel, was warp0-serial)
        {
            int hl  = wid >> 2;
            int kt  = (wid >> 1) & 1;
            int ntp = wid & 1;
            int bn  = lane >> 2;
            int bk2 = (lane & 3) * 2;
            uint4 o;
#pragma unroll
            for (int ii = 0; ii < 2; ii++) {
                int n  = (ntp * 2 + ii) * 8 + bn;
                int k0 = kt * 16 + bk2;
                float w0 = W1[(k0    ) * 32 + n];
                float w1 = W1[(k0 + 1) * 32 + n];
                float w8 = W1[(k0 + 8) * 32 + n];
                float w9 = W1[(k0 + 9) * 32 + n];
                u32 r0, r1;
                if (hl == 0) {
                    r0 = pack_h2(w0, w1); r1 = pack_h2(w8, w9);
                } else {
                    r0 = pack_h2(w0 - rhalf(w0), w1 - rhalf(w1));
                    r1 = pack_h2(w8 - rhalf(w8), w9 - rhalf(w9));
                }
                if (ii == 0) { o.x = r0; o.y = r1; }
                else         { o.z = r0; o.w = r1; }
            }
            sFragW[wid][lane] = o;
            if (wid < 2) {
                int ntpb = wid;
                uint4 ob;
                ob.x = __float_as_uint(b1[ntpb * 16     + bk2]);
                ob.y = __float_as_uint(b1[ntpb * 16     + bk2 + 1]);
                ob.z = __float_as_uint(b1[ntpb * 16 + 8 + bk2]);
                ob.w = __float_as_uint(b1[ntpb * 16 + 8 + bk2 + 1]);
                sFragB[ntpb][lane] = ob;
            }
        }
        __syncthreads();

        // A fragments
        u32 abase = (u32)__cvta_generic_to_shared(sStage[wid]);
        u32 laddr = abase + (lane & 15) * ROWB + ((lane >> 4) << 4);
        u32 A[2][2][4];
#pragma unroll
        for (int mt = 0; mt < 2; mt++)
#pragma unroll
            for (int kt = 0; kt < 2; kt++)
                ldsm_x4(A[mt][kt][0], A[mt][kt][1], A[mt][kt][2], A[mt][kt][3],
                        laddr + mt * 16 * ROWB + kt * 32);

        // C init from bias
        float C[2][4][4];
#pragma unroll
        for (int ntp = 0; ntp < 2; ntp++) {
            uint4 ob = sFragB[ntp][lane];
#pragma unroll
            for (int ii = 0; ii < 2; ii++) {
                int nt = ntp * 2 + ii;
                float bb0 = __uint_as_float(ii ? ob.z : ob.x);
                float bb1 = __uint_as_float(ii ? ob.w : ob.y);
#pragma unroll
                for (int mt = 0; mt < 2; mt++) {
                    C[mt][nt][0] = bb0; C[mt][nt][1] = bb1;
                    C[mt][nt][2] = bb0; C[mt][nt][3] = bb1;
                }
            }
        }

        // 32 HMMA (W1 exact via hi+lo)
#pragma unroll
        for (int hl = 0; hl < 2; hl++)
#pragma unroll
            for (int kt = 0; kt < 2; kt++)
#pragma unroll
                for (int ntp = 0; ntp < 2; ntp++) {
                    uint4 fw = sFragW[hl * 4 + kt * 2 + ntp][lane];
#pragma unroll
                    for (int mt = 0; mt < 2; mt++) {
                        mma16816(C[mt][ntp * 2 + 0], A[mt][kt], fw.x, fw.y);
                        mma16816(C[mt][ntp * 2 + 1], A[mt][kt], fw.z, fw.w);
                    }
                }

        __syncwarp();
        // epilogue: restage C as fp16 pixel rows
#pragma unroll
        for (int mt = 0; mt < 2; mt++)
#pragma unroll
            for (int nt = 0; nt < 4; nt++) {
                u32 h01 = pack_h2(C[mt][nt][0], C[mt][nt][1]);
                u32 h23 = pack_h2(C[mt][nt][2], C[mt][nt][3]);
                int r0   = mt * 16 + (lane >> 2);
                int colb = nt * 16 + (lane & 3) * 4;
                *(u32*)(sStage[wid] + r0 * ROWB + colb)       = h01;
                *(u32*)(sStage[wid] + (r0 + 8) * ROWB + colb) = h23;
            }
        __syncwarp();

        const uint4* grow = (const uint4*)(sStage[wid] + lane * ROWB);
        uint4* gbase = (uint4*)g_Gh;
#pragma unroll
        for (int pp = 0; pp < 4; pp++)
            gbase[(size_t)pp * (NV * HW_F) + p0 + lane] = grow[pp];

    } else if (blockIdx.x < GEMM_BLOCKS + MSUM_BLOCKS) {
        int idx = (blockIdx.x - GEMM_BLOCKS) * 256 + tid;
        int k = idx & 63, j = (idx >> 6) & 63, v = idx >> 12;

        const float* K = Ks + v * 9;
        const float* P = poses + v * 12;
        float M[12];
#pragma unroll
        for (int r = 0; r < 3; r++)
#pragma unroll
            for (int c = 0; c < 4; c++)
                M[r * 4 + c] = K[r * 3 + 0] * P[0 * 4 + c] +
                               K[r * 3 + 1] * P[1 * 4 + c] +
                               K[r * 3 + 2] * P[2 * 4 + c];

        float img_wf = (float)(*pw), img_hf = (float)(*ph);
        float y = (float)j * VOXEL_F + HALF_F + bbox[1];
        float z = (float)k * VOXEL_F + HALF_F + bbox[2];

        float s = 0.f;
        for (int i = 0; i < RESO; i++) {
            float x  = (float)i * VOXEL_F + HALF_F + bbox[0];
            float px = M[0] * x + M[1] * y + M[2]  * z + M[3];
            float py = M[4] * x + M[5] * y + M[6]  * z + M[7];
            float pz = M[8] * x + M[9] * y + M[10] * z + M[11];
            float u  = px / pz, vv = py / pz;
            float gx = u / img_wf - 1.f, gy = vv / img_hf - 1.f;
            float ix = (gx + 1.f) * 0.5f * (float)(W_F - 1);
            float iy = (gy + 1.f) * 0.5f * (float)(H_F - 1);
            float m = (ix >= 0.f && ix <= (float)(W_F - 1) &&
                       iy >= 0.f && iy <= (float)(H_F - 1) && pz > 0.f) ? 1.f : 0.f;
            s += m;
        }
        g_msum[idx] = s;
    } else {
        // fv_main fragments: 4 uint4 per lane (W2/W3 single fp16, biases)
        if (tid < 32) {
            int lane = tid;
            int bn = lane >> 2;
            int bk = (lane & 3) * 2;
            uint4 o[4];
#pragma unroll
            for (int kt = 0; kt < 2; kt++) {
                int k0 = bk + kt * 16;
                o[kt].x = pack_h2(W2[(k0    ) * 16 + bn],     W2[(k0 + 1) * 16 + bn]);
                o[kt].y = pack_h2(W2[(k0 + 8) * 16 + bn],     W2[(k0 + 9) * 16 + bn]);
                o[kt].z = pack_h2(W2[(k0    ) * 16 + bn + 8], W2[(k0 + 1) * 16 + bn + 8]);
                o[kt].w = pack_h2(W2[(k0 + 8) * 16 + bn + 8], W2[(k0 + 9) * 16 + bn + 8]);
            }
            o[2].x = pack_h2(W3[(bk    ) * 8 + bn], W3[(bk + 1) * 8 + bn]);
            o[2].y = pack_h2(W3[(bk + 8) * 8 + bn], W3[(bk + 9) * 8 + bn]);
            o[2].z = __float_as_uint(b3[bk]);
            o[2].w = __float_as_uint(b3[bk + 1]);
            o[3].x = __float_as_uint(b2[bk]);
            o[3].y = __float_as_uint(b2[bk + 1]);
            o[3].z = __float_as_uint(b2[8 + bk]);
            o[3].w = __float_as_uint(b2[8 + bk + 1]);
#pragma unroll
            for (int q = 0; q < 4; q++)
                ((uint4*)g_frag)[q * 32 + lane] = o[q];
        } else if (tid >= 32 && tid < 128 + 32) {
            int e = tid - 32;
            if (e < 96) {
                int v = e / 12, q = e % 12, r = q >> 2, c = q & 3;
                const float* K = Ks + v * 9;
                const float* P = poses + v * 12;
                g_M[e] = K[r * 3 + 0] * P[0 + c] + K[r * 3 + 1] * P[4 + c] +
                         K[r * 3 + 2] * P[8 + c];
            }
        }
    }
}

// ---------------------------------------------------------------------------
// Main fused kernel: 4 voxel-tiles per block (2 i-tiles x 2 j), fragments in
// registers across tiles, one-pass mean/var reduction.
// grid = (RESO/2, RESO): blockIdx.x = j-pair, blockIdx.y = k.
// ---------------------------------------------------------------------------
#define CSTR 260

__global__ __launch_bounds__(256, 4)
void fv_main(const float* __restrict__ bbox,
             const int* __restrict__ ph,
             const int* __restrict__ pw,
             float* __restrict__ out) {
    __shared__ float sM[NV * 12];
    __shared__ float s_comp[8 * CSTR];
    __shared__ float s_w[NV * 32];
    __shared__ __align__(16) unsigned char sA[NV * 32 * ROWB];

    int tid = threadIdx.x;
    if (tid < 96) sM[tid] = g_M[tid];
    __syncthreads();

    int v    = tid >> 5;
    int lane = tid & 31;
    int bk   = (lane & 3) * 2;
    int k    = blockIdx.y;

    // frags once per block (held in registers across tiles)
    const uint4* gf = (const uint4*)g_frag;
    uint4 f0 = gf[0 * 32 + lane];
    uint4 f1 = gf[1 * 32 + lane];
    uint4 f2 = gf[2 * 32 + lane];
    uint4 f3 = gf[3 * 32 + lane];

    float img_wf = (float)(*pw), img_hf = (float)(*ph);
    float bbx = bbox[0], bby = bbox[1], bbz = bbox[2];
    const float* M = sM + v * 12;

#pragma unroll 1
    for (int t = 0; t < 4; t++) {
        int i0 = (t & 1) * 32;
        int j  = blockIdx.x * 2 + (t >> 1);
        int i  = i0 + lane;

        // ---- projection ----
        float x = (float)i * VOXEL_F + HALF_F + bbx;
        float y = (float)j * VOXEL_F + HALF_F + bby;
        float z = (float)k * VOXEL_F + HALF_F + bbz;

        float px = M[0] * x + M[1] * y + M[2]  * z + M[3];
        float py = M[4] * x + M[5] * y + M[6]  * z + M[7];
        float pz = M[8] * x + M[9] * y + M[10] * z + M[11];

        float u  = px / pz, vv = py / pz;
        float gx = u / img_wf - 1.f, gy = vv / img_hf - 1.f;
        float ix = (gx + 1.f) * 0.5f * (float)(W_F - 1);
        float iy = (gy + 1.f) * 0.5f * (float)(H_F - 1);

        float ix0 = floorf(ix), iy0 = floorf(iy);
        float ax = ix - ix0, ay = iy - iy0;
        float wnw = (1.f - ax) * (1.f - ay);
        float wne = ax * (1.f - ay);
        float wsw = (1.f - ax) * ay;
        float wse = ax * ay;
        float mask = (ix >= 0.f && ix <= (float)(W_F - 1) &&
                      iy >= 0.f && iy <= (float)(H_F - 1) && pz > 0.f) ? 1.f : 0.f;

        int cx0 = (int)fminf(fmaxf(ix0,       0.f), (float)(W_F - 1));
        int cx1 = (int)fminf(fmaxf(ix0 + 1.f, 0.f), (float)(W_F - 1));
        int cy0 = (int)fminf(fmaxf(iy0,       0.f), (float)(H_F - 1));
        int cy1 = (int)fminf(fmaxf(iy0 + 1.f, 0.f), (float)(H_F - 1));

        int p00 = (v * H_F + cy0) * W_F + cx0;
        int p01 = (v * H_F + cy0) * W_F + cx1;
        int p10 = (v * H_F + cy1) * W_F + cx0;
        int p11 = (v * H_F + cy1) * W_F + cx1;

        __half2 wnwh = __float2half2_rn(wnw);
        __half2 wneh = __float2half2_rn(wne);
        __half2 wswh = __float2half2_rn(wsw);
        __half2 wseh = __float2half2_rn(wse);
        __half2 zeroh = __float2half2_rn(0.f);

        // ---- gather + interp + ReLU -> staging ----
        unsigned char* myrow = sA + (v * 32 + lane) * ROWB;
        const uint4* gbase = (const uint4*)g_Gh;
#pragma unroll
        for (int pp = 0; pp < 4; pp++) {
            const uint4* plane = gbase + (size_t)pp * (NV * HW_F);
            uint4 a = plane[p00], b = plane[p01], c = plane[p10], d = plane[p11];
            const u32* au = &a.x; const u32* bu = &b.x;
            const u32* cu = &c.x; const u32* du = &d.x;
            u32 hq[4];
#pragma unroll
            for (int q = 0; q < 4; q++) {
                __half2 ha = *(const __half2*)&au[q];
                __half2 hb = *(const __half2*)&bu[q];
                __half2 hc = *(const __half2*)&cu[q];
                __half2 hd = *(const __half2*)&du[q];
                __half2 r = __hmul2(wnwh, ha);
                r = __hfma2(wneh, hb, r);
                r = __hfma2(wswh, hc, r);
                r = __hfma2(wseh, hd, r);
                r = __hmax2(r, zeroh);
                hq[q] = *(const u32*)&r;
            }
            ((uint4*)myrow)[pp] = make_uint4(hq[0], hq[1], hq[2], hq[3]);
        }

        __syncwarp();

        // ---- A fragments ----
        u32 abase = (u32)__cvta_generic_to_shared(sA + v * 32 * ROWB);
        u32 laddr = abase + (lane & 15) * ROWB + ((lane >> 4) << 4);
        u32 A[2][2][4];
#pragma unroll
        for (int mt = 0; mt < 2; mt++)
#pragma unroll
            for (int kt = 0; kt < 2; kt++)
                ldsm_x4(A[mt][kt][0], A[mt][kt][1], A[mt][kt][2], A[mt][kt][3],
                        laddr + mt * 16 * ROWB + kt * 32);

        // ---- layer 2 (8 HMMA, fp16 weights) ----
        float C2[2][2][4];
#pragma unroll
        for (int mt = 0; mt < 2; mt++) {
            C2[mt][0][0] = __uint_as_float(f3.x); C2[mt][0][1] = __uint_as_float(f3.y);
            C2[mt][0][2] = __uint_as_float(f3.x); C2[mt][0][3] = __uint_as_float(f3.y);
            C2[mt][1][0] = __uint_as_float(f3.z); C2[mt][1][1] = __uint_as_float(f3.w);
            C2[mt][1][2] = __uint_as_float(f3.z); C2[mt][1][3] = __uint_as_float(f3.w);
        }
#pragma unroll
        for (int mt = 0; mt < 2; mt++) {
            mma16816(C2[mt][0], A[mt][0], f0.x, f0.y);
            mma16816(C2[mt][1], A[mt][0], f0.z, f0.w);
            mma16816(C2[mt][0], A[mt][1], f1.x, f1.y);
            mma16816(C2[mt][1], A[mt][1], f1.z, f1.w);
        }

        // ---- layer 3 (2 HMMA) ----
        float C3[2][4];
        {
            float bb0 = __uint_as_float(f2.z);
            float bb1 = __uint_as_float(f2.w);
#pragma unroll
            for (int mt = 0; mt < 2; mt++) {
                u32 A3[4];
                A3[0] = pack_h2(fmaxf(C2[mt][0][0], 0.f), fmaxf(C2[mt][0][1], 0.f));
                A3[1] = pack_h2(fmaxf(C2[mt][0][2], 0.f), fmaxf(C2[mt][0][3], 0.f));
                A3[2] = pack_h2(fmaxf(C2[mt][1][0], 0.f), fmaxf(C2[mt][1][1], 0.f));
                A3[3] = pack_h2(fmaxf(C2[mt][1][2], 0.f), fmaxf(C2[mt][1][3], 0.f));
                C3[mt][0] = bb0; C3[mt][1] = bb1; C3[mt][2] = bb0; C3[mt][3] = bb1;
                mma16816(C3[mt], A3, f2.x, f2.y);
            }
        }

        // ---- weight ----
        float S = g_msum[v * (RESO * RESO) + j * RESO + k];
        float w = mask / (S + 1e-8f);
        s_w[v * 32 + lane] = w;

        // ---- scatter (conflict-free padded stride) ----
#pragma unroll
        for (int mt = 0; mt < 2; mt++) {
            int r0 = (lane >> 2) + mt * 16;
            s_comp[(bk    ) * CSTR + v * 32 + r0    ] = C3[mt][0];
            s_comp[(bk + 1) * CSTR + v * 32 + r0    ] = C3[mt][1];
            s_comp[(bk    ) * CSTR + v * 32 + r0 + 8] = C3[mt][2];
            s_comp[(bk + 1) * CSTR + v * 32 + r0 + 8] = C3[mt][3];
        }

        __syncthreads();

        // ---- one-pass weighted mean/var across views ----
        {
            int vox2 = tid & 31;
            int ch   = tid >> 5;
            float s1 = 0.f, s2 = 0.f, sw = 0.f;
#pragma unroll
            for (int v2 = 0; v2 < NV; v2++) {
                float ww = s_w[v2 * 32 + vox2];
                float cc = s_comp[ch * CSTR + v2 * 32 + vox2];
                s1 += ww * cc;
                s2 += ww * cc * cc;
                sw += ww;
            }
            float mean = s1;
            float var  = s2 + s1 * s1 * (sw - 2.f);
            int i_out = i0 + vox2;
            out[(( ch      * RESO + k) * RESO + j) * RESO + i_out] = mean;
            out[(((ch + 8) * RESO + k) * RESO + j) * RESO + i_out] = var;
        }
        __syncthreads();
    }
}

// ---------------------------------------------------------------------------
extern "C" void kernel_launch(void* const* d_in, const int* in_sizes, int n_in,
                              void* d_out, int out_size) {
    const float* feats = (const float*)d_in[0];
    const float* poses = (const float*)d_in[1];
    const float* Ks    = (const float*)d_in[2];
    const float* bbox  = (const float*)d_in[3];
    const int*   ph    = (const int*)d_in[4];
    const int*   pw    = (const int*)d_in[5];
    const float* W1 = (const float*)d_in[6];
    const float* b1 = (const float*)d_in[7];
    const float* W2 = (const float*)d_in[8];
    const float* b2 = (const float*)d_in[9];
    const float* W3 = (const float*)d_in[10];
    const float* b3 = (const float*)d_in[11];
    float* out = (float*)d_out;

    prep_kernel<<<GEMM_BLOCKS + MSUM_BLOCKS + 1, 256>>>(
        feats, W1, b1, Ks, poses, bbox, ph, pw, W2, b2, W3, b3);

    dim3 mg(RESO / 2, RESO);
    fv_main<<<mg, 256>>>(bbox, ph, pw, out);
}

// round 12
// speedup vs baseline: 1.0255x; 1.0255x over previous
#include <cuda_runtime.h>
#include <cuda_fp16.h>

#define NV   8
#define C_CH 32
#define H_F  128
#define W_F  128
#define HW_F (H_F * W_F)
#define RESO 64

#define VOXEL_F ((float)(0.3/64.0))
#define HALF_F  ((float)(0.3/128.0))

typedef unsigned long long u64;
typedef unsigned u32;

// ---- helpers ----
__device__ __forceinline__ u32 pack_h2(float lo, float hi) {
    u32 r; asm("cvt.rn.f16x2.f32 %0, %1, %2;" : "=r"(r) : "f"(hi), "f"(lo)); return r;
}
__device__ __forceinline__ float rhalf(float x) {
    return __half2float(__float2half_rn(x));
}
__device__ __forceinline__ void ldsm_x4(u32& r0, u32& r1, u32& r2, u32& r3, u32 addr) {
    asm volatile("ldmatrix.sync.aligned.m8n8.x4.shared.b16 {%0,%1,%2,%3}, [%4];"
                 : "=r"(r0), "=r"(r1), "=r"(r2), "=r"(r3) : "r"(addr));
}
__device__ __forceinline__ void mma16816(float* c, const u32* a, u32 b0, u32 b1) {
    asm volatile("mma.sync.aligned.m16n8k16.row.col.f32.f16.f16.f32 "
                 "{%0,%1,%2,%3}, {%4,%5,%6,%7}, {%8,%9}, {%0,%1,%2,%3};"
                 : "+f"(c[0]), "+f"(c[1]), "+f"(c[2]), "+f"(c[3])
                 : "r"(a[0]), "r"(a[1]), "r"(a[2]), "r"(a[3]), "r"(b0), "r"(b1));
}

// Scratch
__device__ __align__(16) u32 g_Gh[4 * NV * HW_F * 4];   // fp16 plane-split G
__device__ float g_msum[NV * RESO * RESO];
__device__ __align__(16) u32 g_frag[4 * 32 * 4];        // fv_main per-lane frags
__device__ float g_M[NV * 12];

#define GEMM_BLOCKS 512
#define MSUM_BLOCKS 128
#define ROWB 80

// ---------------------------------------------------------------------------
// Prep kernel (unchanged from R11): HMMA G-GEMM / msum / fragment precompute.
// ---------------------------------------------------------------------------
__global__ __launch_bounds__(256, 3)
void prep_kernel(const float* __restrict__ feats,
                 const float* __restrict__ W1,
                 const float* __restrict__ b1,
                 const float* __restrict__ Ks,
                 const float* __restrict__ poses,
                 const float* __restrict__ bbox,
                 const int* __restrict__ ph,
                 const int* __restrict__ pw,
                 const float* __restrict__ W2, const float* __restrict__ b2,
                 const float* __restrict__ W3, const float* __restrict__ b3) {
    int tid = threadIdx.x;
    if (blockIdx.x < GEMM_BLOCKS) {
        __shared__ __align__(16) uint4 sFragW[8][32];
        __shared__ __align__(16) uint4 sFragB[2][32];
        __shared__ __align__(16) unsigned char sStage[8][32 * ROWB];

        int wid  = tid >> 5;
        int lane = tid & 31;
        int p0 = blockIdx.x * 256 + wid * 32;
        int v  = p0 >> 14;
        int pl = p0 & (HW_F - 1);
        const float* fp = feats + (size_t)v * C_CH * HW_F + pl + lane;

        u32 hq[16];
#pragma unroll
        for (int c2 = 0; c2 < 16; c2++) {
            float f0 = fp[(2 * c2    ) * HW_F];
            float f1 = fp[(2 * c2 + 1) * HW_F];
            hq[c2] = pack_h2(f0, f1);
        }
        {
            uint4* myrow = (uint4*)(sStage[wid] + lane * ROWB);
#pragma unroll
            for (int q = 0; q < 4; q++)
                myrow[q] = make_uint4(hq[q*4+0], hq[q*4+1], hq[q*4+2], hq[q*4+3]);
        }

        {
            int hl  = wid >> 2;
            int kt  = (wid >> 1) & 1;
            int ntp = wid & 1;
            int bn  = lane >> 2;
            int bk2 = (lane & 3) * 2;
            uint4 o;
#pragma unroll
            for (int ii = 0; ii < 2; ii++) {
                int n  = (ntp * 2 + ii) * 8 + bn;
                int k0 = kt * 16 + bk2;
                float w0 = W1[(k0    ) * 32 + n];
                float w1 = W1[(k0 + 1) * 32 + n];
                float w8 = W1[(k0 + 8) * 32 + n];
                float w9 = W1[(k0 + 9) * 32 + n];
                u32 r0, r1;
                if (hl == 0) {
                    r0 = pack_h2(w0, w1); r1 = pack_h2(w8, w9);
                } else {
                    r0 = pack_h2(w0 - rhalf(w0), w1 - rhalf(w1));
                    r1 = pack_h2(w8 - rhalf(w8), w9 - rhalf(w9));
                }
                if (ii == 0) { o.x = r0; o.y = r1; }
                else         { o.z = r0; o.w = r1; }
            }
            sFragW[wid][lane] = o;
            if (wid < 2) {
                int ntpb = wid;
                uint4 ob;
                ob.x = __float_as_uint(b1[ntpb * 16     + bk2]);
                ob.y = __float_as_uint(b1[ntpb * 16     + bk2 + 1]);
                ob.z = __float_as_uint(b1[ntpb * 16 + 8 + bk2]);
                ob.w = __float_as_uint(b1[ntpb * 16 + 8 + bk2 + 1]);
                sFragB[ntpb][lane] = ob;
            }
        }
        __syncthreads();

        u32 abase = (u32)__cvta_generic_to_shared(sStage[wid]);
        u32 laddr = abase + (lane & 15) * ROWB + ((lane >> 4) << 4);
        u32 A[2][2][4];
#pragma unroll
        for (int mt = 0; mt < 2; mt++)
#pragma unroll
            for (int kt = 0; kt < 2; kt++)
                ldsm_x4(A[mt][kt][0], A[mt][kt][1], A[mt][kt][2], A[mt][kt][3],
                        laddr + mt * 16 * ROWB + kt * 32);

        float C[2][4][4];
#pragma unroll
        for (int ntp = 0; ntp < 2; ntp++) {
            uint4 ob = sFragB[ntp][lane];
#pragma unroll
            for (int ii = 0; ii < 2; ii++) {
                int nt = ntp * 2 + ii;
                float bb0 = __uint_as_float(ii ? ob.z : ob.x);
                float bb1 = __uint_as_float(ii ? ob.w : ob.y);
#pragma unroll
                for (int mt = 0; mt < 2; mt++) {
                    C[mt][nt][0] = bb0; C[mt][nt][1] = bb1;
                    C[mt][nt][2] = bb0; C[mt][nt][3] = bb1;
                }
            }
        }

#pragma unroll
        for (int hl = 0; hl < 2; hl++)
#pragma unroll
            for (int kt = 0; kt < 2; kt++)
#pragma unroll
                for (int ntp = 0; ntp < 2; ntp++) {
                    uint4 fw = sFragW[hl * 4 + kt * 2 + ntp][lane];
#pragma unroll
                    for (int mt = 0; mt < 2; mt++) {
                        mma16816(C[mt][ntp * 2 + 0], A[mt][kt], fw.x, fw.y);
                        mma16816(C[mt][ntp * 2 + 1], A[mt][kt], fw.z, fw.w);
                    }
                }

        __syncwarp();
#pragma unroll
        for (int mt = 0; mt < 2; mt++)
#pragma unroll
            for (int nt = 0; nt < 4; nt++) {
                u32 h01 = pack_h2(C[mt][nt][0], C[mt][nt][1]);
                u32 h23 = pack_h2(C[mt][nt][2], C[mt][nt][3]);
                int r0   = mt * 16 + (lane >> 2);
                int colb = nt * 16 + (lane & 3) * 4;
                *(u32*)(sStage[wid] + r0 * ROWB + colb)       = h01;
                *(u32*)(sStage[wid] + (r0 + 8) * ROWB + colb) = h23;
            }
        __syncwarp();

        const uint4* grow = (const uint4*)(sStage[wid] + lane * ROWB);
        uint4* gbase = (uint4*)g_Gh;
#pragma unroll
        for (int pp = 0; pp < 4; pp++)
            gbase[(size_t)pp * (NV * HW_F) + p0 + lane] = grow[pp];

    } else if (blockIdx.x < GEMM_BLOCKS + MSUM_BLOCKS) {
        int idx = (blockIdx.x - GEMM_BLOCKS) * 256 + tid;
        int k = idx & 63, j = (idx >> 6) & 63, v = idx >> 12;

        const float* K = Ks + v * 9;
        const float* P = poses + v * 12;
        float M[12];
#pragma unroll
        for (int r = 0; r < 3; r++)
#pragma unroll
            for (int c = 0; c < 4; c++)
                M[r * 4 + c] = K[r * 3 + 0] * P[0 * 4 + c] +
                               K[r * 3 + 1] * P[1 * 4 + c] +
                               K[r * 3 + 2] * P[2 * 4 + c];

        float img_wf = (float)(*pw), img_hf = (float)(*ph);
        float y = (float)j * VOXEL_F + HALF_F + bbox[1];
        float z = (float)k * VOXEL_F + HALF_F + bbox[2];

        float s = 0.f;
        for (int i = 0; i < RESO; i++) {
            float x  = (float)i * VOXEL_F + HALF_F + bbox[0];
            float px = M[0] * x + M[1] * y + M[2]  * z + M[3];
            float py = M[4] * x + M[5] * y + M[6]  * z + M[7];
            float pz = M[8] * x + M[9] * y + M[10] * z + M[11];
            float u  = px / pz, vv = py / pz;
            float gx = u / img_wf - 1.f, gy = vv / img_hf - 1.f;
            float ix = (gx + 1.f) * 0.5f * (float)(W_F - 1);
            float iy = (gy + 1.f) * 0.5f * (float)(H_F - 1);
            float m = (ix >= 0.f && ix <= (float)(W_F - 1) &&
                       iy >= 0.f && iy <= (float)(H_F - 1) && pz > 0.f) ? 1.f : 0.f;
            s += m;
        }
        g_msum[idx] = s;
    } else {
        if (tid < 32) {
            int lane = tid;
            int bn = lane >> 2;
            int bk = (lane & 3) * 2;
            uint4 o[4];
#pragma unroll
            for (int kt = 0; kt < 2; kt++) {
                int k0 = bk + kt * 16;
                o[kt].x = pack_h2(W2[(k0    ) * 16 + bn],     W2[(k0 + 1) * 16 + bn]);
                o[kt].y = pack_h2(W2[(k0 + 8) * 16 + bn],     W2[(k0 + 9) * 16 + bn]);
                o[kt].z = pack_h2(W2[(k0    ) * 16 + bn + 8], W2[(k0 + 1) * 16 + bn + 8]);
                o[kt].w = pack_h2(W2[(k0 + 8) * 16 + bn + 8], W2[(k0 + 9) * 16 + bn + 8]);
            }
            o[2].x = pack_h2(W3[(bk    ) * 8 + bn], W3[(bk + 1) * 8 + bn]);
            o[2].y = pack_h2(W3[(bk + 8) * 8 + bn], W3[(bk + 9) * 8 + bn]);
            o[2].z = __float_as_uint(b3[bk]);
            o[2].w = __float_as_uint(b3[bk + 1]);
            o[3].x = __float_as_uint(b2[bk]);
            o[3].y = __float_as_uint(b2[bk + 1]);
            o[3].z = __float_as_uint(b2[8 + bk]);
            o[3].w = __float_as_uint(b2[8 + bk + 1]);
#pragma unroll
            for (int q = 0; q < 4; q++)
                ((uint4*)g_frag)[q * 32 + lane] = o[q];
        } else if (tid >= 32 && tid < 128 + 32) {
            int e = tid - 32;
            if (e < 96) {
                int v = e / 12, q = e % 12, r = q >> 2, c = q & 3;
                const float* K = Ks + v * 9;
                const float* P = poses + v * 12;
                g_M[e] = K[r * 3 + 0] * P[0 + c] + K[r * 3 + 1] * P[4 + c] +
                         K[r * 3 + 2] * P[8 + c];
            }
        }
    }
}

// ---------------------------------------------------------------------------
// Main fused kernel: R10 structure (1 tile/block, minimal barriers) +
// single-fp16 frags + one-pass mean/var + M via warp-uniform LDG.
// ---------------------------------------------------------------------------
#define CSTR 260

__global__ __launch_bounds__(256, 4)
void fv_main(const float* __restrict__ bbox,
             const int* __restrict__ ph,
             const int* __restrict__ pw,
             float* __restrict__ out) {
    __shared__ float s_comp[8 * CSTR];
    __shared__ float s_w[NV * 32];
    __shared__ __align__(16) unsigned char sA[NV * 32 * ROWB];

    int tid  = threadIdx.x;
    int v    = tid >> 5;
    int lane = tid & 31;
    int bk   = (lane & 3) * 2;
    int i = blockIdx.x * 32 + lane;
    int j = blockIdx.y;
    int k = blockIdx.z;

    // M: warp-uniform broadcast loads (L1-hot after first wave)
    const float* M = g_M + v * 12;
    float m0 = __ldg(M+0),  m1 = __ldg(M+1),  m2  = __ldg(M+2),  m3  = __ldg(M+3);
    float m4 = __ldg(M+4),  m5 = __ldg(M+5),  m6  = __ldg(M+6),  m7  = __ldg(M+7);
    float m8 = __ldg(M+8),  m9 = __ldg(M+9),  m10 = __ldg(M+10), m11 = __ldg(M+11);

    float x = (float)i * VOXEL_F + HALF_F + bbox[0];
    float y = (float)j * VOXEL_F + HALF_F + bbox[1];
    float z = (float)k * VOXEL_F + HALF_F + bbox[2];

    float px = m0 * x + m1 * y + m2  * z + m3;
    float py = m4 * x + m5 * y + m6  * z + m7;
    float pz = m8 * x + m9 * y + m10 * z + m11;

    float img_wf = (float)(*pw), img_hf = (float)(*ph);
    float u  = px / pz, vv = py / pz;
    float gx = u / img_wf - 1.f, gy = vv / img_hf - 1.f;
    float ix = (gx + 1.f) * 0.5f * (float)(W_F - 1);
    float iy = (gy + 1.f) * 0.5f * (float)(H_F - 1);

    float ix0 = floorf(ix), iy0 = floorf(iy);
    float ax = ix - ix0, ay = iy - iy0;
    float wnw = (1.f - ax) * (1.f - ay);
    float wne = ax * (1.f - ay);
    float wsw = (1.f - ax) * ay;
    float wse = ax * ay;
    float mask = (ix >= 0.f && ix <= (float)(W_F - 1) &&
                  iy >= 0.f && iy <= (float)(H_F - 1) && pz > 0.f) ? 1.f : 0.f;

    int cx0 = (int)fminf(fmaxf(ix0,       0.f), (float)(W_F - 1));
    int cx1 = (int)fminf(fmaxf(ix0 + 1.f, 0.f), (float)(W_F - 1));
    int cy0 = (int)fminf(fmaxf(iy0,       0.f), (float)(H_F - 1));
    int cy1 = (int)fminf(fmaxf(iy0 + 1.f, 0.f), (float)(H_F - 1));

    int p00 = (v * H_F + cy0) * W_F + cx0;
    int p01 = (v * H_F + cy0) * W_F + cx1;
    int p10 = (v * H_F + cy1) * W_F + cx0;
    int p11 = (v * H_F + cy1) * W_F + cx1;

    __half2 wnwh = __float2half2_rn(wnw);
    __half2 wneh = __float2half2_rn(wne);
    __half2 wswh = __float2half2_rn(wsw);
    __half2 wseh = __float2half2_rn(wse);
    __half2 zeroh = __float2half2_rn(0.f);

    // ---- gather + interp + ReLU -> staging ----
    unsigned char* myrow = sA + (v * 32 + lane) * ROWB;
    const uint4* gbase = (const uint4*)g_Gh;
#pragma unroll
    for (int pp = 0; pp < 4; pp++) {
        const uint4* plane = gbase + (size_t)pp * (NV * HW_F);
        uint4 a = plane[p00], b = plane[p01], c = plane[p10], d = plane[p11];
        const u32* au = &a.x; const u32* bu = &b.x;
        const u32* cu = &c.x; const u32* du = &d.x;
        u32 hq[4];
#pragma unroll
        for (int q = 0; q < 4; q++) {
            __half2 ha = *(const __half2*)&au[q];
            __half2 hb = *(const __half2*)&bu[q];
            __half2 hc = *(const __half2*)&cu[q];
            __half2 hd = *(const __half2*)&du[q];
            __half2 r = __hmul2(wnwh, ha);
            r = __hfma2(wneh, hb, r);
            r = __hfma2(wswh, hc, r);
            r = __hfma2(wseh, hd, r);
            r = __hmax2(r, zeroh);
            hq[q] = *(const u32*)&r;
        }
        ((uint4*)myrow)[pp] = make_uint4(hq[0], hq[1], hq[2], hq[3]);
    }

    __syncwarp();

    // ---- A fragments ----
    u32 abase = (u32)__cvta_generic_to_shared(sA + v * 32 * ROWB);
    u32 laddr = abase + (lane & 15) * ROWB + ((lane >> 4) << 4);
    u32 A[2][2][4];
#pragma unroll
    for (int mt = 0; mt < 2; mt++)
#pragma unroll
        for (int kt = 0; kt < 2; kt++)
            ldsm_x4(A[mt][kt][0], A[mt][kt][1], A[mt][kt][2], A[mt][kt][3],
                    laddr + mt * 16 * ROWB + kt * 32);

    // ---- fragments (L1-resident, loaded at use) ----
    const uint4* gf = (const uint4*)g_frag;

    // ---- layer 2 (8 HMMA, fp16 weights) ----
    float C2[2][2][4];
    {
        uint4 fb2 = gf[3 * 32 + lane];
#pragma unroll
        for (int mt = 0; mt < 2; mt++) {
            C2[mt][0][0] = __uint_as_float(fb2.x); C2[mt][0][1] = __uint_as_float(fb2.y);
            C2[mt][0][2] = __uint_as_float(fb2.x); C2[mt][0][3] = __uint_as_float(fb2.y);
            C2[mt][1][0] = __uint_as_float(fb2.z); C2[mt][1][1] = __uint_as_float(fb2.w);
            C2[mt][1][2] = __uint_as_float(fb2.z); C2[mt][1][3] = __uint_as_float(fb2.w);
        }
    }
#pragma unroll
    for (int kt = 0; kt < 2; kt++) {
        uint4 fw = gf[kt * 32 + lane];
#pragma unroll
        for (int mt = 0; mt < 2; mt++) {
            mma16816(C2[mt][0], A[mt][kt], fw.x, fw.y);
            mma16816(C2[mt][1], A[mt][kt], fw.z, fw.w);
        }
    }

    // ---- layer 3 (2 HMMA) ----
    float C3[2][4];
    {
        uint4 f2 = gf[2 * 32 + lane];
        float bb0 = __uint_as_float(f2.z);
        float bb1 = __uint_as_float(f2.w);
#pragma unroll
        for (int mt = 0; mt < 2; mt++) {
            u32 A3[4];
            A3[0] = pack_h2(fmaxf(C2[mt][0][0], 0.f), fmaxf(C2[mt][0][1], 0.f));
            A3[1] = pack_h2(fmaxf(C2[mt][0][2], 0.f), fmaxf(C2[mt][0][3], 0.f));
            A3[2] = pack_h2(fmaxf(C2[mt][1][0], 0.f), fmaxf(C2[mt][1][1], 0.f));
            A3[3] = pack_h2(fmaxf(C2[mt][1][2], 0.f), fmaxf(C2[mt][1][3], 0.f));
            C3[mt][0] = bb0; C3[mt][1] = bb1; C3[mt][2] = bb0; C3[mt][3] = bb1;
            mma16816(C3[mt], A3, f2.x, f2.y);
        }
    }

    // ---- weight ----
    float S = g_msum[v * (RESO * RESO) + j * RESO + k];
    float w = mask / (S + 1e-8f);
    s_w[v * 32 + lane] = w;

    // ---- scatter (conflict-free padded stride) ----
#pragma unroll
    for (int mt = 0; mt < 2; mt++) {
        int r0 = (lane >> 2) + mt * 16;
        s_comp[(bk    ) * CSTR + v * 32 + r0    ] = C3[mt][0];
        s_comp[(bk + 1) * CSTR + v * 32 + r0    ] = C3[mt][1];
        s_comp[(bk    ) * CSTR + v * 32 + r0 + 8] = C3[mt][2];
        s_comp[(bk + 1) * CSTR + v * 32 + r0 + 8] = C3[mt][3];
    }

    __syncthreads();

    // ---- one-pass weighted mean/var across views ----
    int vox2 = tid & 31;
    int ch   = tid >> 5;
    float s1 = 0.f, s2 = 0.f, sw = 0.f;
#pragma unroll
    for (int v2 = 0; v2 < NV; v2++) {
        float ww = s_w[v2 * 32 + vox2];
        float cc = s_comp[ch * CSTR + v2 * 32 + vox2];
        s1 += ww * cc;
        s2 += ww * cc * cc;
        sw += ww;
    }
    float mean = s1;
    float var  = s2 + s1 * s1 * (sw - 2.f);

    int i_out = blockIdx.x * 32 + vox2;
    out[(( ch      * RESO + k) * RESO + j) * RESO + i_out] = mean;
    out[(((ch + 8) * RESO + k) * RESO + j) * RESO + i_out] = var;
}

// ---------------------------------------------------------------------------
extern "C" void kernel_launch(void* const* d_in, const int* in_sizes, int n_in,
                              void* d_out, int out_size) {
    const float* feats = (const float*)d_in[0];
    const float* poses = (const float*)d_in[1];
    const float* Ks    = (const float*)d_in[2];
    const float* bbox  = (const float*)d_in[3];
    const int*   ph    = (const int*)d_in[4];
    const int*   pw    = (const int*)d_in[5];
    const float* W1 = (const float*)d_in[6];
    const float* b1 = (const float*)d_in[7];
    const float* W2 = (const float*)d_in[8];
    const float* b2 = (const float*)d_in[9];
    const float* W3 = (const float*)d_in[10];
    const float* b3 = (const float*)d_in[11];
    float* out = (float*)d_out;

    prep_kernel<<<GEMM_BLOCKS + MSUM_BLOCKS + 1, 256>>>(
        feats, W1, b1, Ks, poses, bbox, ph, pw, W2, b2, W3, b3);

    dim3 mg(RESO / 32, RESO, RESO);
    fv_main<<<mg, 256>>>(bbox, ph, pw, out);
}

// round 13
// speedup vs baseline: 1.2208x; 1.1905x over previous
#include <cuda_runtime.h>
#include <cuda_fp16.h>

#define NV   8
#define C_CH 32
#define H_F  128
#define W_F  128
#define HW_F (H_F * W_F)
#define RESO 64

#define VOXEL_F ((float)(0.3/64.0))
#define HALF_F  ((float)(0.3/128.0))

typedef unsigned long long u64;
typedef unsigned u32;

// ---- helpers ----
__device__ __forceinline__ u32 pack_h2(float lo, float hi) {
    u32 r; asm("cvt.rn.f16x2.f32 %0, %1, %2;" : "=r"(r) : "f"(hi), "f"(lo)); return r;
}
__device__ __forceinline__ float rhalf(float x) {
    return __half2float(__float2half_rn(x));
}
__device__ __forceinline__ void ldsm_x4(u32& r0, u32& r1, u32& r2, u32& r3, u32 addr) {
    asm volatile("ldmatrix.sync.aligned.m8n8.x4.shared.b16 {%0,%1,%2,%3}, [%4];"
                 : "=r"(r0), "=r"(r1), "=r"(r2), "=r"(r3) : "r"(addr));
}
__device__ __forceinline__ void mma16816(float* c, const u32* a, u32 b0, u32 b1) {
    asm volatile("mma.sync.aligned.m16n8k16.row.col.f32.f16.f16.f32 "
                 "{%0,%1,%2,%3}, {%4,%5,%6,%7}, {%8,%9}, {%0,%1,%2,%3};"
                 : "+f"(c[0]), "+f"(c[1]), "+f"(c[2]), "+f"(c[3])
                 : "r"(a[0]), "r"(a[1]), "r"(a[2]), "r"(a[3]), "r"(b0), "r"(b1));
}

// Scratch
__device__ __align__(16) u32 g_Gh[4 * NV * HW_F * 4];   // fp16 plane-split G
__device__ __align__(16) u32 g_frag[4 * 32 * 4];        // fv_main per-lane frags
__device__ float g_M[NV * 12];

#define GEMM_BLOCKS 512
#define ROWB 80

// ---------------------------------------------------------------------------
// Prep kernel: [0,512) HMMA G-GEMM; block 512 = fragment/M precompute.
// (msum pass eliminated — computed in fv_main via ballot/popc.)
// ---------------------------------------------------------------------------
__global__ __launch_bounds__(256, 3)
void prep_kernel(const float* __restrict__ feats,
                 const float* __restrict__ W1,
                 const float* __restrict__ b1,
                 const float* __restrict__ Ks,
                 const float* __restrict__ poses,
                 const float* __restrict__ W2, const float* __restrict__ b2,
                 const float* __restrict__ W3, const float* __restrict__ b3) {
    int tid = threadIdx.x;
    if (blockIdx.x < GEMM_BLOCKS) {
        __shared__ __align__(16) uint4 sFragW[8][32];
        __shared__ __align__(16) uint4 sFragB[2][32];
        __shared__ __align__(16) unsigned char sStage[8][32 * ROWB];

        int wid  = tid >> 5;
        int lane = tid & 31;
        int p0 = blockIdx.x * 256 + wid * 32;
        int v  = p0 >> 14;
        int pl = p0 & (HW_F - 1);
        const float* fp = feats + (size_t)v * C_CH * HW_F + pl + lane;

        u32 hq[16];
#pragma unroll
        for (int c2 = 0; c2 < 16; c2++) {
            float f0 = fp[(2 * c2    ) * HW_F];
            float f1 = fp[(2 * c2 + 1) * HW_F];
            hq[c2] = pack_h2(f0, f1);
        }
        {
            uint4* myrow = (uint4*)(sStage[wid] + lane * ROWB);
#pragma unroll
            for (int q = 0; q < 4; q++)
                myrow[q] = make_uint4(hq[q*4+0], hq[q*4+1], hq[q*4+2], hq[q*4+3]);
        }

        {
            int hl  = wid >> 2;
            int kt  = (wid >> 1) & 1;
            int ntp = wid & 1;
            int bn  = lane >> 2;
            int bk2 = (lane & 3) * 2;
            uint4 o;
#pragma unroll
            for (int ii = 0; ii < 2; ii++) {
                int n  = (ntp * 2 + ii) * 8 + bn;
                int k0 = kt * 16 + bk2;
                float w0 = W1[(k0    ) * 32 + n];
                float w1 = W1[(k0 + 1) * 32 + n];
                float w8 = W1[(k0 + 8) * 32 + n];
                float w9 = W1[(k0 + 9) * 32 + n];
                u32 r0, r1;
                if (hl == 0) {
                    r0 = pack_h2(w0, w1); r1 = pack_h2(w8, w9);
                } else {
                    r0 = pack_h2(w0 - rhalf(w0), w1 - rhalf(w1));
                    r1 = pack_h2(w8 - rhalf(w8), w9 - rhalf(w9));
                }
                if (ii == 0) { o.x = r0; o.y = r1; }
                else         { o.z = r0; o.w = r1; }
            }
            sFragW[wid][lane] = o;
            if (wid < 2) {
                int ntpb = wid;
                uint4 ob;
                ob.x = __float_as_uint(b1[ntpb * 16     + bk2]);
                ob.y = __float_as_uint(b1[ntpb * 16     + bk2 + 1]);
                ob.z = __float_as_uint(b1[ntpb * 16 + 8 + bk2]);
                ob.w = __float_as_uint(b1[ntpb * 16 + 8 + bk2 + 1]);
                sFragB[ntpb][lane] = ob;
            }
        }
        __syncthreads();

        u32 abase = (u32)__cvta_generic_to_shared(sStage[wid]);
        u32 laddr = abase + (lane & 15) * ROWB + ((lane >> 4) << 4);
        u32 A[2][2][4];
#pragma unroll
        for (int mt = 0; mt < 2; mt++)
#pragma unroll
            for (int kt = 0; kt < 2; kt++)
                ldsm_x4(A[mt][kt][0], A[mt][kt][1], A[mt][kt][2], A[mt][kt][3],
                        laddr + mt * 16 * ROWB + kt * 32);

        float C[2][4][4];
#pragma unroll
        for (int ntp = 0; ntp < 2; ntp++) {
            uint4 ob = sFragB[ntp][lane];
#pragma unroll
            for (int ii = 0; ii < 2; ii++) {
                int nt = ntp * 2 + ii;
                float bb0 = __uint_as_float(ii ? ob.z : ob.x);
                float bb1 = __uint_as_float(ii ? ob.w : ob.y);
#pragma unroll
                for (int mt = 0; mt < 2; mt++) {
                    C[mt][nt][0] = bb0; C[mt][nt][1] = bb1;
                    C[mt][nt][2] = bb0; C[mt][nt][3] = bb1;
                }
            }
        }

#pragma unroll
        for (int hl = 0; hl < 2; hl++)
#pragma unroll
            for (int kt = 0; kt < 2; kt++)
#pragma unroll
                for (int ntp = 0; ntp < 2; ntp++) {
                    uint4 fw = sFragW[hl * 4 + kt * 2 + ntp][lane];
#pragma unroll
                    for (int mt = 0; mt < 2; mt++) {
                        mma16816(C[mt][ntp * 2 + 0], A[mt][kt], fw.x, fw.y);
                        mma16816(C[mt][ntp * 2 + 1], A[mt][kt], fw.z, fw.w);
                    }
                }

        __syncwarp();
#pragma unroll
        for (int mt = 0; mt < 2; mt++)
#pragma unroll
            for (int nt = 0; nt < 4; nt++) {
                u32 h01 = pack_h2(C[mt][nt][0], C[mt][nt][1]);
                u32 h23 = pack_h2(C[mt][nt][2], C[mt][nt][3]);
                int r0   = mt * 16 + (lane >> 2);
                int colb = nt * 16 + (lane & 3) * 4;
                *(u32*)(sStage[wid] + r0 * ROWB + colb)       = h01;
                *(u32*)(sStage[wid] + (r0 + 8) * ROWB + colb) = h23;
            }
        __syncwarp();

        const uint4* grow = (const uint4*)(sStage[wid] + lane * ROWB);
        uint4* gbase = (uint4*)g_Gh;
#pragma unroll
        for (int pp = 0; pp < 4; pp++)
            gbase[(size_t)pp * (NV * HW_F) + p0 + lane] = grow[pp];

    } else {
        if (tid < 32) {
            int lane = tid;
            int bn = lane >> 2;
            int bk = (lane & 3) * 2;
            uint4 o[4];
#pragma unroll
            for (int kt = 0; kt < 2; kt++) {
                int k0 = bk + kt * 16;
                o[kt].x = pack_h2(W2[(k0    ) * 16 + bn],     W2[(k0 + 1) * 16 + bn]);
                o[kt].y = pack_h2(W2[(k0 + 8) * 16 + bn],     W2[(k0 + 9) * 16 + bn]);
                o[kt].z = pack_h2(W2[(k0    ) * 16 + bn + 8], W2[(k0 + 1) * 16 + bn + 8]);
                o[kt].w = pack_h2(W2[(k0 + 8) * 16 + bn + 8], W2[(k0 + 9) * 16 + bn + 8]);
            }
            o[2].x = pack_h2(W3[(bk    ) * 8 + bn], W3[(bk + 1) * 8 + bn]);
            o[2].y = pack_h2(W3[(bk + 8) * 8 + bn], W3[(bk + 9) * 8 + bn]);
            o[2].z = __float_as_uint(b3[bk]);
            o[2].w = __float_as_uint(b3[bk + 1]);
            o[3].x = __float_as_uint(b2[bk]);
            o[3].y = __float_as_uint(b2[bk + 1]);
            o[3].z = __float_as_uint(b2[8 + bk]);
            o[3].w = __float_as_uint(b2[8 + bk + 1]);
#pragma unroll
            for (int q = 0; q < 4; q++)
                ((uint4*)g_frag)[q * 32 + lane] = o[q];
        } else if (tid >= 32 && tid < 128 + 32) {
            int e = tid - 32;
            if (e < 96) {
                int v = e / 12, q = e % 12, r = q >> 2, c = q & 3;
                const float* K = Ks + v * 9;
                const float* P = poses + v * 12;
                g_M[e] = K[r * 3 + 0] * P[0 + c] + K[r * 3 + 1] * P[4 + c] +
                         K[r * 3 + 2] * P[8 + c];
            }
        }
    }
}

// ---------------------------------------------------------------------------
// Main fused kernel: block = (j,k), 2 i-tiles (full i-range), ONE barrier.
// msum computed in-kernel via ballot+popc (exact). grid = (RESO, RESO).
// ---------------------------------------------------------------------------
#define CSTR 260

__global__ __launch_bounds__(256, 4)
void fv_main(const float* __restrict__ bbox,
             const int* __restrict__ ph,
             const int* __restrict__ pw,
             float* __restrict__ out) {
    __shared__ float s_comp[2][8 * CSTR];
    __shared__ float s_w[2][NV * 32];
    __shared__ float sInv[NV];
    __shared__ __align__(16) unsigned char sA[NV * 32 * ROWB];

    int tid  = threadIdx.x;
    int v    = tid >> 5;
    int lane = tid & 31;
    int bk   = (lane & 3) * 2;
    int j = blockIdx.x;
    int k = blockIdx.y;

    // per-block constants (amortized over both tiles)
    const float* M = g_M + v * 12;
    float m0 = __ldg(M+0),  m1 = __ldg(M+1),  m2  = __ldg(M+2),  m3  = __ldg(M+3);
    float m4 = __ldg(M+4),  m5 = __ldg(M+5),  m6  = __ldg(M+6),  m7  = __ldg(M+7);
    float m8 = __ldg(M+8),  m9 = __ldg(M+9),  m10 = __ldg(M+10), m11 = __ldg(M+11);
    float img_wf = (float)(*pw), img_hf = (float)(*ph);
    float bbx = bbox[0], bby = bbox[1], bbz = bbox[2];

    const uint4* gf = (const uint4*)g_frag;
    uint4 f0 = gf[0 * 32 + lane];
    uint4 f1 = gf[1 * 32 + lane];
    uint4 f2 = gf[2 * 32 + lane];
    uint4 fb = gf[3 * 32 + lane];

    float y = (float)j * VOXEL_F + HALF_F + bby;
    float z = (float)k * VOXEL_F + HALF_F + bbz;

    int cnt = 0;

#pragma unroll 1
    for (int t = 0; t < 2; t++) {
        int i = t * 32 + lane;

        // ---- projection ----
        float x = (float)i * VOXEL_F + HALF_F + bbx;
        float px = m0 * x + m1 * y + m2  * z + m3;
        float py = m4 * x + m5 * y + m6  * z + m7;
        float pz = m8 * x + m9 * y + m10 * z + m11;

        float u  = px / pz, vv = py / pz;
        float gx = u / img_wf - 1.f, gy = vv / img_hf - 1.f;
        float ix = (gx + 1.f) * 0.5f * (float)(W_F - 1);
        float iy = (gy + 1.f) * 0.5f * (float)(H_F - 1);

        float ix0 = floorf(ix), iy0 = floorf(iy);
        float ax = ix - ix0, ay = iy - iy0;
        float wnw = (1.f - ax) * (1.f - ay);
        float wne = ax * (1.f - ay);
        float wsw = (1.f - ax) * ay;
        float wse = ax * ay;
        float mask = (ix >= 0.f && ix <= (float)(W_F - 1) &&
                      iy >= 0.f && iy <= (float)(H_F - 1) && pz > 0.f) ? 1.f : 0.f;

        // per-warp mask count (== reference msum, exact)
        unsigned bal = __ballot_sync(0xffffffffu, mask != 0.f);
        cnt += __popc(bal);

        int cx0 = (int)fminf(fmaxf(ix0,       0.f), (float)(W_F - 1));
        int cx1 = (int)fminf(fmaxf(ix0 + 1.f, 0.f), (float)(W_F - 1));
        int cy0 = (int)fminf(fmaxf(iy0,       0.f), (float)(H_F - 1));
        int cy1 = (int)fminf(fmaxf(iy0 + 1.f, 0.f), (float)(H_F - 1));

        int p00 = (v * H_F + cy0) * W_F + cx0;
        int p01 = (v * H_F + cy0) * W_F + cx1;
        int p10 = (v * H_F + cy1) * W_F + cx0;
        int p11 = (v * H_F + cy1) * W_F + cx1;

        __half2 wnwh = __float2half2_rn(wnw);
        __half2 wneh = __float2half2_rn(wne);
        __half2 wswh = __float2half2_rn(wsw);
        __half2 wseh = __float2half2_rn(wse);
        __half2 zeroh = __float2half2_rn(0.f);

        // ---- gather + interp + ReLU -> staging (per-warp private) ----
        unsigned char* myrow = sA + (v * 32 + lane) * ROWB;
        const uint4* gbase = (const uint4*)g_Gh;
#pragma unroll
        for (int pp = 0; pp < 4; pp++) {
            const uint4* plane = gbase + (size_t)pp * (NV * HW_F);
            uint4 a = plane[p00], b = plane[p01], c = plane[p10], d = plane[p11];
            const u32* au = &a.x; const u32* bu = &b.x;
            const u32* cu = &c.x; const u32* du = &d.x;
            u32 hq[4];
#pragma unroll
            for (int q = 0; q < 4; q++) {
                __half2 ha = *(const __half2*)&au[q];
                __half2 hb = *(const __half2*)&bu[q];
                __half2 hc = *(const __half2*)&cu[q];
                __half2 hd = *(const __half2*)&du[q];
                __half2 r = __hmul2(wnwh, ha);
                r = __hfma2(wneh, hb, r);
                r = __hfma2(wswh, hc, r);
                r = __hfma2(wseh, hd, r);
                r = __hmax2(r, zeroh);
                hq[q] = *(const u32*)&r;
            }
            ((uint4*)myrow)[pp] = make_uint4(hq[0], hq[1], hq[2], hq[3]);
        }

        __syncwarp();

        // ---- A fragments ----
        u32 abase = (u32)__cvta_generic_to_shared(sA + v * 32 * ROWB);
        u32 laddr = abase + (lane & 15) * ROWB + ((lane >> 4) << 4);
        u32 A[2][2][4];
#pragma unroll
        for (int mt = 0; mt < 2; mt++)
#pragma unroll
            for (int kt = 0; kt < 2; kt++)
                ldsm_x4(A[mt][kt][0], A[mt][kt][1], A[mt][kt][2], A[mt][kt][3],
                        laddr + mt * 16 * ROWB + kt * 32);

        // ---- layer 2 (8 HMMA) ----
        float C2[2][2][4];
#pragma unroll
        for (int mt = 0; mt < 2; mt++) {
            C2[mt][0][0] = __uint_as_float(fb.x); C2[mt][0][1] = __uint_as_float(fb.y);
            C2[mt][0][2] = __uint_as_float(fb.x); C2[mt][0][3] = __uint_as_float(fb.y);
            C2[mt][1][0] = __uint_as_float(fb.z); C2[mt][1][1] = __uint_as_float(fb.w);
            C2[mt][1][2] = __uint_as_float(fb.z); C2[mt][1][3] = __uint_as_float(fb.w);
        }
#pragma unroll
        for (int mt = 0; mt < 2; mt++) {
            mma16816(C2[mt][0], A[mt][0], f0.x, f0.y);
            mma16816(C2[mt][1], A[mt][0], f0.z, f0.w);
            mma16816(C2[mt][0], A[mt][1], f1.x, f1.y);
            mma16816(C2[mt][1], A[mt][1], f1.z, f1.w);
        }

        // ---- layer 3 (2 HMMA) ----
        float C3[2][4];
        {
            float bb0 = __uint_as_float(f2.z);
            float bb1 = __uint_as_float(f2.w);
#pragma unroll
            for (int mt = 0; mt < 2; mt++) {
                u32 A3[4];
                A3[0] = pack_h2(fmaxf(C2[mt][0][0], 0.f), fmaxf(C2[mt][0][1], 0.f));
                A3[1] = pack_h2(fmaxf(C2[mt][0][2], 0.f), fmaxf(C2[mt][0][3], 0.f));
                A3[2] = pack_h2(fmaxf(C2[mt][1][0], 0.f), fmaxf(C2[mt][1][1], 0.f));
                A3[3] = pack_h2(fmaxf(C2[mt][1][2], 0.f), fmaxf(C2[mt][1][3], 0.f));
                C3[mt][0] = bb0; C3[mt][1] = bb1; C3[mt][2] = bb0; C3[mt][3] = bb1;
                mma16816(C3[mt], A3, f2.x, f2.y);
            }
        }

        // ---- stash mask + comp (weight applied after S known) ----
        s_w[t][v * 32 + lane] = mask;
#pragma unroll
        for (int mt = 0; mt < 2; mt++) {
            int r0 = (lane >> 2) + mt * 16;
            s_comp[t][(bk    ) * CSTR + v * 32 + r0    ] = C3[mt][0];
            s_comp[t][(bk + 1) * CSTR + v * 32 + r0    ] = C3[mt][1];
            s_comp[t][(bk    ) * CSTR + v * 32 + r0 + 8] = C3[mt][2];
            s_comp[t][(bk + 1) * CSTR + v * 32 + r0 + 8] = C3[mt][3];
        }

        __syncwarp();   // sA write-after-read fence for next tile
    }

    // per-view 1/(S+eps); w = mask * inv == mask/(S+eps) exactly (mask in {0,1})
    if (lane == 0) sInv[v] = 1.f / ((float)cnt + 1e-8f);

    __syncthreads();

    // ---- one-pass weighted mean/var, both tiles ----
    int vox2 = tid & 31;
    int ch   = tid >> 5;
#pragma unroll
    for (int t = 0; t < 2; t++) {
        float s1 = 0.f, s2 = 0.f, sw = 0.f;
#pragma unroll
        for (int v2 = 0; v2 < NV; v2++) {
            float ww = s_w[t][v2 * 32 + vox2] * sInv[v2];
            float cc = s_comp[t][ch * CSTR + v2 * 32 + vox2];
            s1 += ww * cc;
            s2 += ww * cc * cc;
            sw += ww;
        }
        float mean = s1;
        float var  = s2 + s1 * s1 * (sw - 2.f);
        int i_out = t * 32 + vox2;
        out[(( ch      * RESO + k) * RESO + j) * RESO + i_out] = mean;
        out[(((ch + 8) * RESO + k) * RESO + j) * RESO + i_out] = var;
    }
}

// ---------------------------------------------------------------------------
extern "C" void kernel_launch(void* const* d_in, const int* in_sizes, int n_in,
                              void* d_out, int out_size) {
    const float* feats = (const float*)d_in[0];
    const float* poses = (const float*)d_in[1];
    const float* Ks    = (const float*)d_in[2];
    const float* bbox  = (const float*)d_in[3];
    const int*   ph    = (const int*)d_in[4];
    const int*   pw    = (const int*)d_in[5];
    const float* W1 = (const float*)d_in[6];
    const float* b1 = (const float*)d_in[7];
    const float* W2 = (const float*)d_in[8];
    const float* b2 = (const float*)d_in[9];
    const float* W3 = (const float*)d_in[10];
    const float* b3 = (const float*)d_in[11];
    float* out = (float*)d_out;

    prep_kernel<<<GEMM_BLOCKS + 1, 256>>>(feats, W1, b1, Ks, poses, W2, b2, W3, b3);

    dim3 mg(RESO, RESO);
    fv_main<<<mg, 256>>>(bbox, ph, pw, out);
}